// round 1
// baseline (speedup 1.0000x reference)
#include <cuda_runtime.h>

// Problem constants
#define Tt    1024
#define Bb    8
#define Ee    1024
#define Hh    16
#define Dh    64
#define QKVF  3072           // 3*E
#define MROWS 8192           // T*B

// Scratch (device globals — no runtime allocation allowed)
__device__ float g_qkv[(size_t)MROWS * QKVF];   // [T*B, 3E]
__device__ float g_attn[(size_t)MROWS * Ee];    // [T*B, E]

// ---------------------------------------------------------------------------
// SGEMM (NT): C[M,N] = A[M,K] * B[N,K]^T + bias[N]
// 128x128x16 block tile, 256 threads, 8x8 per-thread micro-tile.
// ---------------------------------------------------------------------------
__global__ void __launch_bounds__(256, 2) sgemm_nt_bias(
    const float* __restrict__ A, const float* __restrict__ Bw,
    const float* __restrict__ bias, float* __restrict__ C,
    int M, int N, int K)
{
    __shared__ float As[16][132];
    __shared__ float Bs[16][132];

    const int tid = threadIdx.x;
    const int tx  = tid & 15;
    const int ty  = tid >> 4;
    const int m0  = blockIdx.y * 128;
    const int n0  = blockIdx.x * 128;

    const int lrow = tid >> 2;   // 0..63
    const int lq   = tid & 3;    // 0..3 (float4 chunk within 16-wide k slab)

    const float* Aptr = A  + (size_t)(m0 + lrow) * K + lq * 4;
    const float* Bptr = Bw + (size_t)(n0 + lrow) * K + lq * 4;

    float acc[8][8];
    #pragma unroll
    for (int i = 0; i < 8; i++)
        #pragma unroll
        for (int j = 0; j < 8; j++) acc[i][j] = 0.0f;

    for (int kb = 0; kb < K; kb += 16) {
        float4 a0 = *(const float4*)(Aptr + kb);
        float4 a1 = *(const float4*)(Aptr + (size_t)64 * K + kb);
        float4 b0 = *(const float4*)(Bptr + kb);
        float4 b1 = *(const float4*)(Bptr + (size_t)64 * K + kb);

        As[lq*4+0][lrow]    = a0.x; As[lq*4+1][lrow]    = a0.y;
        As[lq*4+2][lrow]    = a0.z; As[lq*4+3][lrow]    = a0.w;
        As[lq*4+0][lrow+64] = a1.x; As[lq*4+1][lrow+64] = a1.y;
        As[lq*4+2][lrow+64] = a1.z; As[lq*4+3][lrow+64] = a1.w;

        Bs[lq*4+0][lrow]    = b0.x; Bs[lq*4+1][lrow]    = b0.y;
        Bs[lq*4+2][lrow]    = b0.z; Bs[lq*4+3][lrow]    = b0.w;
        Bs[lq*4+0][lrow+64] = b1.x; Bs[lq*4+1][lrow+64] = b1.y;
        Bs[lq*4+2][lrow+64] = b1.z; Bs[lq*4+3][lrow+64] = b1.w;

        __syncthreads();

        #pragma unroll
        for (int k = 0; k < 16; ++k) {
            float4 af0 = *(const float4*)&As[k][ty*4];
            float4 af1 = *(const float4*)&As[k][64 + ty*4];
            float4 bf0 = *(const float4*)&Bs[k][tx*4];
            float4 bf1 = *(const float4*)&Bs[k][64 + tx*4];
            float ar[8] = {af0.x, af0.y, af0.z, af0.w, af1.x, af1.y, af1.z, af1.w};
            float br[8] = {bf0.x, bf0.y, bf0.z, bf0.w, bf1.x, bf1.y, bf1.z, bf1.w};
            #pragma unroll
            for (int i = 0; i < 8; i++)
                #pragma unroll
                for (int j = 0; j < 8; j++)
                    acc[i][j] += ar[i] * br[j];
        }
        __syncthreads();
    }

    float4 bia0 = *(const float4*)&bias[n0 + tx*4];
    float4 bia1 = *(const float4*)&bias[n0 + 64 + tx*4];
    float bb0[4] = {bia0.x, bia0.y, bia0.z, bia0.w};
    float bb1[4] = {bia1.x, bia1.y, bia1.z, bia1.w};

    #pragma unroll
    for (int i = 0; i < 8; i++) {
        int row = m0 + ((i < 4) ? (ty*4 + i) : (64 + ty*4 + i - 4));
        float4 v0, v1;
        v0.x = acc[i][0] + bb0[0]; v0.y = acc[i][1] + bb0[1];
        v0.z = acc[i][2] + bb0[2]; v0.w = acc[i][3] + bb0[3];
        v1.x = acc[i][4] + bb1[0]; v1.y = acc[i][5] + bb1[1];
        v1.z = acc[i][6] + bb1[2]; v1.w = acc[i][7] + bb1[3];
        *(float4*)&C[(size_t)row * N + n0 + tx*4]      = v0;
        *(float4*)&C[(size_t)row * N + n0 + 64 + tx*4] = v1;
    }
}

// ---------------------------------------------------------------------------
// Flash attention (fp32, causal). One block per (64-query tile, b*H+h).
// 256 threads; thread (tx,ty) owns rows r=4ty+i, cols c=tx+16j.
// Q/K/V tiles in 48KB static smem; P overlays K's buffer; online softmax in
// registers with width-16 shuffles; O accumulator in registers.
// ---------------------------------------------------------------------------
__global__ void __launch_bounds__(256, 2) flash_kernel()
{
    __shared__ float Qs[64*64];   // plain  [row][d]
    __shared__ float KSs[64*64];  // K: xor-swizzled chunks; later P: plain [r][c]
    __shared__ float Vs[64*64];   // plain  [row][d]

    const int tid = threadIdx.x;
    const int tx  = tid & 15;
    const int ty  = tid >> 4;
    const int qt  = blockIdx.x;
    const int bh  = blockIdx.y;
    const int b   = bh >> 4;     // bh / H
    const int h   = bh & 15;     // bh % H

    const int q0 = qt * 64;

    // Load Q tile (scaled by DH^-0.5 = 0.125)
    #pragma unroll
    for (int rep = 0; rep < 4; ++rep) {
        int idx = tid + rep * 256;
        int row = idx >> 4;
        int q4  = (idx & 15) * 4;
        const float* src = g_qkv + ((size_t)(q0 + row) * Bb + b) * QKVF + h * Dh + q4;
        float4 v = *(const float4*)src;
        v.x *= 0.125f; v.y *= 0.125f; v.z *= 0.125f; v.w *= 0.125f;
        *(float4*)&Qs[row * 64 + q4] = v;
    }

    float o[4][4];
    float mrow[4], lrow[4];
    #pragma unroll
    for (int i = 0; i < 4; i++) {
        mrow[i] = -1e30f; lrow[i] = 0.0f;
        #pragma unroll
        for (int j = 0; j < 4; j++) o[i][j] = 0.0f;
    }

    for (int kt = 0; kt <= qt; ++kt) {
        const int k0 = kt * 64;
        __syncthreads();  // previous iteration's smem consumers done

        // Load K (swizzled) and V
        #pragma unroll
        for (int rep = 0; rep < 4; ++rep) {
            int idx = tid + rep * 256;
            int row = idx >> 4;
            int q   = idx & 15;
            const float* kp = g_qkv + ((size_t)(k0 + row) * Bb + b) * QKVF + Ee + h * Dh + q * 4;
            float4 kv = *(const float4*)kp;
            int sw = q ^ (row & 7);
            *(float4*)&KSs[row * 64 + sw * 4] = kv;
            float4 vv = *(const float4*)(kp + Ee);
            *(float4*)&Vs[row * 64 + q * 4] = vv;
        }
        __syncthreads();

        // S = Q K^T  (rows 4ty+i, cols tx+16j)
        float sacc[4][4];
        #pragma unroll
        for (int i = 0; i < 4; i++)
            #pragma unroll
            for (int j = 0; j < 4; j++) sacc[i][j] = 0.0f;

        #pragma unroll
        for (int d0 = 0; d0 < 64; d0 += 4) {
            const int cd = d0 >> 2;
            float a[4][4];
            #pragma unroll
            for (int i = 0; i < 4; i++) {
                float4 t = *(const float4*)&Qs[(ty*4 + i) * 64 + d0];
                a[i][0] = t.x; a[i][1] = t.y; a[i][2] = t.z; a[i][3] = t.w;
            }
            #pragma unroll
            for (int j = 0; j < 4; j++) {
                int c = tx + 16*j;
                float4 t = *(const float4*)&KSs[c * 64 + ((cd ^ (c & 7)) << 2)];
                #pragma unroll
                for (int i = 0; i < 4; i++)
                    sacc[i][j] += a[i][0]*t.x + a[i][1]*t.y + a[i][2]*t.z + a[i][3]*t.w;
            }
        }

        // Causal mask (diagonal tile only; k0 == q0 there)
        if (kt == qt) {
            #pragma unroll
            for (int i = 0; i < 4; i++)
                #pragma unroll
                for (int j = 0; j < 4; j++)
                    if (tx + 16*j > ty*4 + i) sacc[i][j] = -1e30f;
        }

        // Online softmax update
        float rmax[4];
        #pragma unroll
        for (int i = 0; i < 4; i++)
            rmax[i] = fmaxf(fmaxf(sacc[i][0], sacc[i][1]), fmaxf(sacc[i][2], sacc[i][3]));
        #pragma unroll
        for (int off = 8; off >= 1; off >>= 1)
            #pragma unroll
            for (int i = 0; i < 4; i++)
                rmax[i] = fmaxf(rmax[i], __shfl_xor_sync(0xffffffffu, rmax[i], off, 16));

        float alpha[4], rsum[4];
        #pragma unroll
        for (int i = 0; i < 4; i++) {
            float mn = fmaxf(mrow[i], rmax[i]);
            alpha[i] = __expf(mrow[i] - mn);
            mrow[i]  = mn;
            float s = 0.0f;
            #pragma unroll
            for (int j = 0; j < 4; j++) {
                float p = __expf(sacc[i][j] - mn);
                sacc[i][j] = p;
                s += p;
            }
            rsum[i] = s;
        }
        #pragma unroll
        for (int off = 8; off >= 1; off >>= 1)
            #pragma unroll
            for (int i = 0; i < 4; i++)
                rsum[i] += __shfl_xor_sync(0xffffffffu, rsum[i], off, 16);
        #pragma unroll
        for (int i = 0; i < 4; i++) {
            lrow[i] = lrow[i] * alpha[i] + rsum[i];
            #pragma unroll
            for (int j = 0; j < 4; j++) o[i][j] *= alpha[i];
        }

        __syncthreads();  // all K-buffer readers done before overwriting as P

        // Write P into KSs (plain layout)
        #pragma unroll
        for (int i = 0; i < 4; i++)
            #pragma unroll
            for (int j = 0; j < 4; j++)
                KSs[(ty*4 + i) * 64 + tx + 16*j] = sacc[i][j];
        __syncthreads();

        // O += P V
        #pragma unroll
        for (int c0 = 0; c0 < 64; c0 += 4) {
            float a[4][4];
            #pragma unroll
            for (int i = 0; i < 4; i++) {
                float4 t = *(const float4*)&KSs[(ty*4 + i) * 64 + c0];
                a[i][0] = t.x; a[i][1] = t.y; a[i][2] = t.z; a[i][3] = t.w;
            }
            #pragma unroll
            for (int cc = 0; cc < 4; cc++) {
                float v[4];
                #pragma unroll
                for (int j = 0; j < 4; j++)
                    v[j] = Vs[(c0 + cc) * 64 + tx + 16*j];
                #pragma unroll
                for (int i = 0; i < 4; i++)
                    #pragma unroll
                    for (int j = 0; j < 4; j++)
                        o[i][j] += a[i][cc] * v[j];
            }
        }
    }

    // Epilogue: normalize and write [T,B,E]
    #pragma unroll
    for (int i = 0; i < 4; i++) {
        float inv = 1.0f / lrow[i];
        int t = q0 + ty*4 + i;
        float* dst = g_attn + ((size_t)t * Bb + b) * Ee + h * Dh;
        #pragma unroll
        for (int j = 0; j < 4; j++)
            dst[tx + 16*j] = o[i][j] * inv;
    }
}

// ---------------------------------------------------------------------------
// Launch
// ---------------------------------------------------------------------------
extern "C" void kernel_launch(void* const* d_in, const int* in_sizes, int n_in,
                              void* d_out, int out_size)
{
    const float* query = (const float*)d_in[0];
    const float* qkv_w = (const float*)d_in[1];
    const float* qkv_b = (const float*)d_in[2];
    const float* out_w = (const float*)d_in[3];
    const float* out_b = (const float*)d_in[4];
    float* out = (float*)d_out;

    void* p_qkv  = nullptr;
    void* p_attn = nullptr;
    cudaGetSymbolAddress(&p_qkv,  g_qkv);
    cudaGetSymbolAddress(&p_attn, g_attn);

    // 1) QKV projection: [8192,1024] x [3072,1024]^T -> [8192,3072]
    sgemm_nt_bias<<<dim3(QKVF/128, MROWS/128), 256>>>(
        query, qkv_w, qkv_b, (float*)p_qkv, MROWS, QKVF, Ee);

    // 2) Causal flash attention per (query-tile, b*H+h)
    flash_kernel<<<dim3(Tt/64, Bb*Hh), 256>>>();

    // 3) Output projection: [8192,1024] x [1024,1024]^T -> [8192,1024]
    sgemm_nt_bias<<<dim3(Ee/128, MROWS/128), 256>>>(
        (const float*)p_attn, out_w, out_b, out, MROWS, Ee, Ee);
}

// round 2
// speedup vs baseline: 1.7751x; 1.7751x over previous
#include <cuda_runtime.h>
#include <cstdint>

// Problem constants
#define Tt    1024
#define Bb    8
#define Ee    1024
#define Hh    16
#define Dh    64
#define QKVF  3072           // 3*E
#define MROWS 8192           // T*B

// Scratch (device globals — no runtime allocation allowed)
__device__ float g_qkv[(size_t)MROWS * QKVF];   // [T*B, 3E]
__device__ float g_attn[(size_t)MROWS * Ee];    // [T*B, E]

// ---------------------------------------------------------------------------
// Helpers: tf32 convert (round-to-nearest) + m16n8k8 tf32 mma
// ---------------------------------------------------------------------------
__device__ __forceinline__ uint32_t f2tf(float x) {
    uint32_t r;
    asm("cvt.rna.tf32.f32 %0, %1;" : "=r"(r) : "f"(x));
    return r;
}

__device__ __forceinline__ void mma8(float* c,
                                     uint32_t a0, uint32_t a1, uint32_t a2, uint32_t a3,
                                     uint32_t b0, uint32_t b1) {
    asm volatile("mma.sync.aligned.m16n8k8.row.col.f32.tf32.tf32.f32 "
                 "{%0,%1,%2,%3}, {%4,%5,%6,%7}, {%8,%9}, {%0,%1,%2,%3};"
                 : "+f"(c[0]), "+f"(c[1]), "+f"(c[2]), "+f"(c[3])
                 : "r"(a0), "r"(a1), "r"(a2), "r"(a3), "r"(b0), "r"(b1));
}

// ---------------------------------------------------------------------------
// GEMM (NT): C[M,N] = A[M,K] * B[N,K]^T + bias[N], tf32 tensor cores.
// Block 128x128, BK=16, 256 threads = 8 warps (2m x 4n), warp tile 64x32.
// k-permutation: thread t holds k-cols/rows (2t, 2t+1) within each k8 chunk
// (applied identically to A and B fragments -> result unchanged, enables
// 8-byte LDS with per-phase conflict-free banking at pitch GLD=20).
// ---------------------------------------------------------------------------
#define GLD 20

__global__ void __launch_bounds__(256) gemm_tf32(
    const float* __restrict__ A, const float* __restrict__ Bw,
    const float* __restrict__ bias, float* __restrict__ C,
    int M, int N, int K)
{
    __shared__ uint32_t As[2][128 * GLD];
    __shared__ uint32_t Bs[2][128 * GLD];

    const int tid  = threadIdx.x;
    const int lane = tid & 31;
    const int g    = lane >> 2;
    const int t    = lane & 3;
    const int warp = tid >> 5;
    const int wm   = warp & 1;        // 0..1 -> 64-row half
    const int wn   = warp >> 1;       // 0..3 -> 32-col strip
    const int m0   = blockIdx.y * 128;
    const int n0   = blockIdx.x * 128;

    // global load mapping: 2 threads per row, 8 cols each (BK=16)
    const int lr = tid >> 1;
    const int lc = (tid & 1) * 8;
    const float* Ag = A  + (size_t)(m0 + lr) * K + lc;
    const float* Bg = Bw + (size_t)(n0 + lr) * K + lc;

    float acc[4][4][4];
    #pragma unroll
    for (int mt = 0; mt < 4; mt++)
        #pragma unroll
        for (int nt = 0; nt < 4; nt++)
            #pragma unroll
            for (int i = 0; i < 4; i++) acc[mt][nt][i] = 0.0f;

    const int nkt = K >> 4;

    float4 pa0 = *(const float4*)(Ag);
    float4 pa1 = *(const float4*)(Ag + 4);
    float4 pb0 = *(const float4*)(Bg);
    float4 pb1 = *(const float4*)(Bg + 4);

    {   // stage 0 store
        uint32_t* ap = &As[0][lr * GLD + lc];
        *(uint4*)(ap)     = make_uint4(f2tf(pa0.x), f2tf(pa0.y), f2tf(pa0.z), f2tf(pa0.w));
        *(uint4*)(ap + 4) = make_uint4(f2tf(pa1.x), f2tf(pa1.y), f2tf(pa1.z), f2tf(pa1.w));
        uint32_t* bp = &Bs[0][lr * GLD + lc];
        *(uint4*)(bp)     = make_uint4(f2tf(pb0.x), f2tf(pb0.y), f2tf(pb0.z), f2tf(pb0.w));
        *(uint4*)(bp + 4) = make_uint4(f2tf(pb1.x), f2tf(pb1.y), f2tf(pb1.z), f2tf(pb1.w));
    }
    __syncthreads();

    for (int kt = 0; kt < nkt; ++kt) {
        const int st = kt & 1;
        if (kt + 1 < nkt) {
            const float* Ap = Ag + (kt + 1) * 16;
            const float* Bp = Bg + (kt + 1) * 16;
            pa0 = *(const float4*)(Ap);
            pa1 = *(const float4*)(Ap + 4);
            pb0 = *(const float4*)(Bp);
            pb1 = *(const float4*)(Bp + 4);
        }

        #pragma unroll
        for (int ks = 0; ks < 2; ++ks) {
            const int kb = ks * 8 + 2 * t;
            uint2 a_lo[4], a_hi[4], bf[4];
            #pragma unroll
            for (int mt = 0; mt < 4; ++mt) {
                const uint32_t* base = &As[st][(wm * 64 + mt * 16 + g) * GLD + kb];
                a_lo[mt] = *(const uint2*)(base);
                a_hi[mt] = *(const uint2*)(base + 8 * GLD);
            }
            #pragma unroll
            for (int nt = 0; nt < 4; ++nt)
                bf[nt] = *(const uint2*)&Bs[st][(wn * 32 + nt * 8 + g) * GLD + kb];
            #pragma unroll
            for (int mt = 0; mt < 4; ++mt)
                #pragma unroll
                for (int nt = 0; nt < 4; ++nt)
                    mma8(acc[mt][nt],
                         a_lo[mt].x, a_hi[mt].x, a_lo[mt].y, a_hi[mt].y,
                         bf[nt].x, bf[nt].y);
        }

        if (kt + 1 < nkt) {
            const int sn = st ^ 1;
            uint32_t* ap = &As[sn][lr * GLD + lc];
            *(uint4*)(ap)     = make_uint4(f2tf(pa0.x), f2tf(pa0.y), f2tf(pa0.z), f2tf(pa0.w));
            *(uint4*)(ap + 4) = make_uint4(f2tf(pa1.x), f2tf(pa1.y), f2tf(pa1.z), f2tf(pa1.w));
            uint32_t* bp = &Bs[sn][lr * GLD + lc];
            *(uint4*)(bp)     = make_uint4(f2tf(pb0.x), f2tf(pb0.y), f2tf(pb0.z), f2tf(pb0.w));
            *(uint4*)(bp + 4) = make_uint4(f2tf(pb1.x), f2tf(pb1.y), f2tf(pb1.z), f2tf(pb1.w));
            __syncthreads();
        }
    }

    // Epilogue: C fragment cols = 2t, 2t+1 within each n8 tile
    #pragma unroll
    for (int mt = 0; mt < 4; ++mt) {
        const int r0 = m0 + wm * 64 + mt * 16 + g;
        #pragma unroll
        for (int nt = 0; nt < 4; ++nt) {
            const int col = n0 + wn * 32 + nt * 8 + 2 * t;
            const float2 bv = *(const float2*)&bias[col];
            float2 v0 = make_float2(acc[mt][nt][0] + bv.x, acc[mt][nt][1] + bv.y);
            float2 v1 = make_float2(acc[mt][nt][2] + bv.x, acc[mt][nt][3] + bv.y);
            *(float2*)&C[(size_t)r0 * N + col]       = v0;
            *(float2*)&C[(size_t)(r0 + 8) * N + col] = v1;
        }
    }
}

// ---------------------------------------------------------------------------
// Flash attention, tf32 tensor cores, causal.
// Block: 128 threads (4 warps), 64-query tile; warp w owns rows w*16..w*16+15.
// Q fragments preloaded to registers straight from gmem (scaled + tf32).
// K tile in smem [s][d]; V stored transposed [d][s]; same (2t,2t+1)
// k-permutation everywhere, so softmaxed S fragments ARE the P A-fragments
// (no smem round-trip for P).
// ---------------------------------------------------------------------------
#define FLD 72

__global__ void __launch_bounds__(128) flash_tf32()
{
    __shared__ uint32_t Ks[64 * FLD];   // [s][d] tf32
    __shared__ uint32_t Vt[64 * FLD];   // [d][s] tf32

    const int tid  = threadIdx.x;
    const int lane = tid & 31;
    const int g    = lane >> 2;
    const int t    = lane & 3;
    const int w    = tid >> 5;
    const int qt   = blockIdx.x;
    const int bh   = blockIdx.y;
    const int b    = bh >> 4;
    const int h    = bh & 15;
    const int q0   = qt * 64;

    // Preload Q fragments: rows (q0+w*16+g, +8), cols (8ks+2t, +1), *0.125
    uint32_t qa[8][4];
    {
        const size_t row_lo = ((size_t)(q0 + w * 16 + g) * Bb + b) * QKVF + h * Dh;
        const size_t row_hi = row_lo + (size_t)8 * Bb * QKVF;
        #pragma unroll
        for (int ks = 0; ks < 8; ++ks) {
            float2 lo = *(const float2*)&g_qkv[row_lo + ks * 8 + 2 * t];
            float2 hi = *(const float2*)&g_qkv[row_hi + ks * 8 + 2 * t];
            qa[ks][0] = f2tf(lo.x * 0.125f);
            qa[ks][1] = f2tf(hi.x * 0.125f);
            qa[ks][2] = f2tf(lo.y * 0.125f);
            qa[ks][3] = f2tf(hi.y * 0.125f);
        }
    }

    float o[8][4];
    #pragma unroll
    for (int nt = 0; nt < 8; nt++)
        #pragma unroll
        for (int i = 0; i < 4; i++) o[nt][i] = 0.0f;
    float m0v = -1e30f, m1v = -1e30f, l0 = 0.0f, l1 = 0.0f;

    const int kr = tid >> 1;           // 0..63: row for K/V loads
    const int kc = (tid & 1) * 32;     // col base

    for (int kt = 0; kt <= qt; ++kt) {
        __syncthreads();   // prior iteration's smem readers done

        // Load K (row-major) + V (transposed) tiles, cvt to tf32
        {
            const float* Kg = g_qkv + ((size_t)(kt * 64 + kr) * Bb + b) * QKVF + Ee + h * Dh + kc;
            const float* Vg = Kg + Ee;
            #pragma unroll
            for (int j = 0; j < 8; ++j) {
                float4 kv = *(const float4*)(Kg + j * 4);
                *(uint4*)&Ks[kr * FLD + kc + j * 4] =
                    make_uint4(f2tf(kv.x), f2tf(kv.y), f2tf(kv.z), f2tf(kv.w));
                float4 vv = *(const float4*)(Vg + j * 4);
                const int d0 = kc + j * 4;
                Vt[(d0 + 0) * FLD + kr] = f2tf(vv.x);
                Vt[(d0 + 1) * FLD + kr] = f2tf(vv.y);
                Vt[(d0 + 2) * FLD + kr] = f2tf(vv.z);
                Vt[(d0 + 3) * FLD + kr] = f2tf(vv.w);
            }
        }
        __syncthreads();

        // S = Q K^T (warp's 16 rows x 64 cols)
        float s[8][4];
        #pragma unroll
        for (int nt = 0; nt < 8; nt++)
            #pragma unroll
            for (int i = 0; i < 4; i++) s[nt][i] = 0.0f;

        #pragma unroll
        for (int ks = 0; ks < 8; ++ks) {
            #pragma unroll
            for (int nt = 0; nt < 8; ++nt) {
                uint2 kb = *(const uint2*)&Ks[(nt * 8 + g) * FLD + ks * 8 + 2 * t];
                mma8(s[nt], qa[ks][0], qa[ks][1], qa[ks][2], qa[ks][3], kb.x, kb.y);
            }
        }

        // Causal mask (diagonal tile only; same local coords both axes)
        if (kt == qt) {
            const int r_lo = w * 16 + g, r_hi = r_lo + 8;
            #pragma unroll
            for (int nt = 0; nt < 8; ++nt) {
                const int c0 = nt * 8 + 2 * t, c1 = c0 + 1;
                if (c0 > r_lo) s[nt][0] = -1e30f;
                if (c1 > r_lo) s[nt][1] = -1e30f;
                if (c0 > r_hi) s[nt][2] = -1e30f;
                if (c1 > r_hi) s[nt][3] = -1e30f;
            }
        }

        // Online softmax (rows g and g+8; quad = lanes sharing g -> xor 1,2)
        float mx0 = -1e30f, mx1 = -1e30f;
        #pragma unroll
        for (int nt = 0; nt < 8; ++nt) {
            mx0 = fmaxf(mx0, fmaxf(s[nt][0], s[nt][1]));
            mx1 = fmaxf(mx1, fmaxf(s[nt][2], s[nt][3]));
        }
        mx0 = fmaxf(mx0, __shfl_xor_sync(0xffffffffu, mx0, 1));
        mx0 = fmaxf(mx0, __shfl_xor_sync(0xffffffffu, mx0, 2));
        mx1 = fmaxf(mx1, __shfl_xor_sync(0xffffffffu, mx1, 1));
        mx1 = fmaxf(mx1, __shfl_xor_sync(0xffffffffu, mx1, 2));

        const float mn0 = fmaxf(m0v, mx0), mn1 = fmaxf(m1v, mx1);
        const float al0 = __expf(m0v - mn0), al1 = __expf(m1v - mn1);
        m0v = mn0; m1v = mn1;

        float sum0 = 0.0f, sum1 = 0.0f;
        #pragma unroll
        for (int nt = 0; nt < 8; ++nt) {
            s[nt][0] = __expf(s[nt][0] - mn0); sum0 += s[nt][0];
            s[nt][1] = __expf(s[nt][1] - mn0); sum0 += s[nt][1];
            s[nt][2] = __expf(s[nt][2] - mn1); sum1 += s[nt][2];
            s[nt][3] = __expf(s[nt][3] - mn1); sum1 += s[nt][3];
        }
        sum0 += __shfl_xor_sync(0xffffffffu, sum0, 1);
        sum0 += __shfl_xor_sync(0xffffffffu, sum0, 2);
        sum1 += __shfl_xor_sync(0xffffffffu, sum1, 1);
        sum1 += __shfl_xor_sync(0xffffffffu, sum1, 2);
        l0 = l0 * al0 + sum0;
        l1 = l1 * al1 + sum1;

        #pragma unroll
        for (int nt = 0; nt < 8; ++nt) {
            o[nt][0] *= al0; o[nt][1] *= al0;
            o[nt][2] *= al1; o[nt][3] *= al1;
        }

        // O += P V  (P fragments = softmaxed S fragments, reg-resident)
        #pragma unroll
        for (int ks = 0; ks < 8; ++ks) {
            const uint32_t p0 = f2tf(s[ks][0]);   // (g,   2t)
            const uint32_t p1 = f2tf(s[ks][2]);   // (g+8, 2t)
            const uint32_t p2 = f2tf(s[ks][1]);   // (g,   2t+1)
            const uint32_t p3 = f2tf(s[ks][3]);   // (g+8, 2t+1)
            #pragma unroll
            for (int nt = 0; nt < 8; ++nt) {
                uint2 vb = *(const uint2*)&Vt[(nt * 8 + g) * FLD + ks * 8 + 2 * t];
                mma8(o[nt], p0, p1, p2, p3, vb.x, vb.y);
            }
        }
    }

    // Epilogue: normalize, write [T,B,E]
    const float inv0 = 1.0f / l0, inv1 = 1.0f / l1;
    float* dst_lo = g_attn + ((size_t)(q0 + w * 16 + g) * Bb + b) * Ee + h * Dh;
    float* dst_hi = dst_lo + (size_t)8 * Bb * Ee;
    #pragma unroll
    for (int nt = 0; nt < 8; ++nt) {
        const int c = nt * 8 + 2 * t;
        *(float2*)&dst_lo[c] = make_float2(o[nt][0] * inv0, o[nt][1] * inv0);
        *(float2*)&dst_hi[c] = make_float2(o[nt][2] * inv1, o[nt][3] * inv1);
    }
}

// ---------------------------------------------------------------------------
// Launch
// ---------------------------------------------------------------------------
extern "C" void kernel_launch(void* const* d_in, const int* in_sizes, int n_in,
                              void* d_out, int out_size)
{
    const float* query = (const float*)d_in[0];
    const float* qkv_w = (const float*)d_in[1];
    const float* qkv_b = (const float*)d_in[2];
    const float* out_w = (const float*)d_in[3];
    const float* out_b = (const float*)d_in[4];
    float* out = (float*)d_out;

    void* p_qkv  = nullptr;
    void* p_attn = nullptr;
    cudaGetSymbolAddress(&p_qkv,  g_qkv);
    cudaGetSymbolAddress(&p_attn, g_attn);

    // 1) QKV projection: [8192,1024] x [3072,1024]^T -> [8192,3072]
    gemm_tf32<<<dim3(QKVF / 128, MROWS / 128), 256>>>(
        query, qkv_w, qkv_b, (float*)p_qkv, MROWS, QKVF, Ee);

    // 2) Causal flash attention per (query-tile, b*H+h)
    flash_tf32<<<dim3(Tt / 64, Bb * Hh), 128>>>();

    // 3) Output projection: [8192,1024] x [1024,1024]^T -> [8192,1024]
    gemm_tf32<<<dim3(Ee / 128, MROWS / 128), 256>>>(
        (const float*)p_attn, out_w, out_b, out, MROWS, Ee, Ee);
}

// round 4
// speedup vs baseline: 5.5404x; 3.1212x over previous
#include <cuda_runtime.h>
#include <cuda_fp16.h>
#include <cstdint>

// Problem constants
#define Tt    1024
#define Bb    8
#define Ee    1024
#define Hh    16
#define Dh    64
#define QKVF  3072           // 3*E
#define MROWS 8192           // T*B

// Scratch (device globals — no runtime allocation allowed)
__device__ __half g_xh  [(size_t)MROWS * Ee];    // query, fp16
__device__ __half g_w1h [(size_t)QKVF * Ee];     // qkv_w, fp16
__device__ __half g_w2h [(size_t)Ee * Ee];       // out_w, fp16
__device__ __half g_qkvh[(size_t)MROWS * QKVF];  // qkv proj out (Q pre-scaled), fp16
__device__ __half g_atth[(size_t)MROWS * Ee];    // attention out, fp16

// ---------------------------------------------------------------------------
// Helpers
// ---------------------------------------------------------------------------
__device__ __forceinline__ uint32_t packh2(float lo, float hi) {
    __half2 h = __floats2half2_rn(lo, hi);
    return *reinterpret_cast<uint32_t*>(&h);
}

__device__ __forceinline__ void mma16(float* c,
                                      uint32_t a0, uint32_t a1, uint32_t a2, uint32_t a3,
                                      uint32_t b0, uint32_t b1) {
    asm volatile("mma.sync.aligned.m16n8k16.row.col.f32.f16.f16.f32 "
                 "{%0,%1,%2,%3}, {%4,%5,%6,%7}, {%8,%9}, {%0,%1,%2,%3};"
                 : "+f"(c[0]), "+f"(c[1]), "+f"(c[2]), "+f"(c[3])
                 : "r"(a0), "r"(a1), "r"(a2), "r"(a3), "r"(b0), "r"(b1));
}

__device__ __forceinline__ void ldsm4(uint32_t& r0, uint32_t& r1, uint32_t& r2, uint32_t& r3,
                                      uint32_t addr) {
    asm volatile("ldmatrix.sync.aligned.m8n8.x4.shared.b16 {%0,%1,%2,%3}, [%4];"
                 : "=r"(r0), "=r"(r1), "=r"(r2), "=r"(r3) : "r"(addr));
}

__device__ __forceinline__ void ldsm4t(uint32_t& r0, uint32_t& r1, uint32_t& r2, uint32_t& r3,
                                       uint32_t addr) {
    asm volatile("ldmatrix.sync.aligned.m8n8.x4.trans.shared.b16 {%0,%1,%2,%3}, [%4];"
                 : "=r"(r0), "=r"(r1), "=r"(r2), "=r"(r3) : "r"(addr));
}

// ---------------------------------------------------------------------------
// Prepass: fp32 -> fp16 (RN)
// ---------------------------------------------------------------------------
__global__ void cvt_f32_f16(const float4* __restrict__ in, uint2* __restrict__ out, int n4) {
    int i = blockIdx.x * blockDim.x + threadIdx.x;
    if (i < n4) {
        float4 v = in[i];
        uint2 o;
        o.x = packh2(v.x, v.y);
        o.y = packh2(v.z, v.w);
        out[i] = o;
    }
}

// ---------------------------------------------------------------------------
// fp16 tensor-core GEMM (NT): C[M,N] = A[M,K]*B[N,K]^T, epilogue (acc+bias)*scale
// Block 256 thr = 8 warps (2m x 4n), warp tile 64x64, CTA 128x256, BK=32 halfs.
// 3-stage cp.async pipeline (pure 16B copies, inputs already fp16).
// Smem rows: 64B (4 x 16B chunks), chunk swizzle c ^ ((row>>1)&3) -> ldmatrix
// and staging both conflict-free.
// ---------------------------------------------------------------------------
#define BM  128
#define BN  256
#define BKH 32
#define NSG 3
#define ABY (BM * 64)          // 8192
#define BBY (BN * 64)          // 16384
#define STG (ABY + BBY)        // 24576
#define GSM (NSG * STG)        // 73728

__global__ void __launch_bounds__(256) gemm_f16(
    const __half* __restrict__ Ah, const __half* __restrict__ Bh,
    const float* __restrict__ bias, __half* __restrict__ Ch, float* __restrict__ Cf,
    int M, int N, int K, int qscale)
{
    extern __shared__ char smem[];
    const uint32_t sb = (uint32_t)__cvta_generic_to_shared(smem);
    const int tid  = threadIdx.x;
    const int lane = tid & 31;
    const int warp = tid >> 5;
    const int wm = warp & 1;
    const int wn = warp >> 1;
    const int m0 = blockIdx.y * BM;
    const int n0 = blockIdx.x * BN;

    float acc[4][8][4];
    #pragma unroll
    for (int mt = 0; mt < 4; mt++)
        #pragma unroll
        for (int nt = 0; nt < 8; nt++)
            #pragma unroll
            for (int i = 0; i < 4; i++) acc[mt][nt][i] = 0.0f;

    auto load_stage = [&](int s, int c) {
        const uint32_t base = sb + s * STG;
        const int k0 = c * BKH;
        #pragma unroll
        for (int i = 0; i < 6; i++) {
            int q = tid + i * 256;
            uint32_t dst;
            const __half* src;
            if (q < 512) {                   // A: 128 rows x 4 chunks
                int r = q >> 2, ch = q & 3;
                src = Ah + (size_t)(m0 + r) * K + k0 + ch * 8;
                dst = base + r * 64 + ((ch ^ ((r >> 1) & 3)) << 4);
            } else {                         // B: 256 rows x 4 chunks
                int q2 = q - 512;
                int r = q2 >> 2, ch = q2 & 3;
                src = Bh + (size_t)(n0 + r) * K + k0 + ch * 8;
                dst = base + ABY + r * 64 + ((ch ^ ((r >> 1) & 3)) << 4);
            }
            asm volatile("cp.async.cg.shared.global [%0], [%1], 16;" :: "r"(dst), "l"(src));
        }
        asm volatile("cp.async.commit_group;" ::: "memory");
    };

    const int nk = K / BKH;
    load_stage(0, 0);
    load_stage(1, 1);

    const int a_rl = ((lane >> 3) & 1) * 8 + (lane & 7);
    const int a_ck = lane >> 4;
    const int b_rl = ((lane >> 4) & 1) * 8 + (lane & 7);
    const int b_ck = (lane >> 3) & 1;

    for (int c = 0; c < nk; c++) {
        const int s = c % NSG;
        if (c < nk - 1) asm volatile("cp.async.wait_group 1;" ::: "memory");
        else            asm volatile("cp.async.wait_group 0;" ::: "memory");
        __syncthreads();
        if (c + NSG - 1 < nk) load_stage((c + NSG - 1) % NSG, c + NSG - 1);

        const uint32_t abase = sb + s * STG;
        const uint32_t bbase = abase + ABY;
        #pragma unroll
        for (int ks = 0; ks < 2; ks++) {
            uint32_t af[4][4], bf[8][2];
            #pragma unroll
            for (int mt = 0; mt < 4; mt++) {
                int ar = wm * 64 + mt * 16 + a_rl;
                int ch = (2 * ks + a_ck) ^ ((ar >> 1) & 3);
                ldsm4(af[mt][0], af[mt][1], af[mt][2], af[mt][3],
                      abase + ar * 64 + (ch << 4));
            }
            #pragma unroll
            for (int p = 0; p < 4; p++) {
                int br = wn * 64 + p * 16 + b_rl;
                int ch = (2 * ks + b_ck) ^ ((br >> 1) & 3);
                uint32_t r0, r1, r2, r3;
                ldsm4(r0, r1, r2, r3, bbase + br * 64 + (ch << 4));
                bf[2 * p][0] = r0;     bf[2 * p][1] = r1;
                bf[2 * p + 1][0] = r2; bf[2 * p + 1][1] = r3;
            }
            #pragma unroll
            for (int mt = 0; mt < 4; mt++)
                #pragma unroll
                for (int nt = 0; nt < 8; nt++)
                    mma16(acc[mt][nt], af[mt][0], af[mt][1], af[mt][2], af[mt][3],
                          bf[nt][0], bf[nt][1]);
        }
    }

    // Epilogue
    const float scale = (qscale && n0 < Ee) ? 0.125f : 1.0f;
    const int g = lane >> 2, t = lane & 3;
    #pragma unroll
    for (int mt = 0; mt < 4; mt++) {
        const int r0 = m0 + wm * 64 + mt * 16 + g;
        #pragma unroll
        for (int nt = 0; nt < 8; nt++) {
            const int col = n0 + wn * 64 + nt * 8 + 2 * t;
            const float b0 = bias[col], b1 = bias[col + 1];
            float v00 = (acc[mt][nt][0] + b0) * scale;
            float v01 = (acc[mt][nt][1] + b1) * scale;
            float v10 = (acc[mt][nt][2] + b0) * scale;
            float v11 = (acc[mt][nt][3] + b1) * scale;
            if (Ch) {
                *(uint32_t*)&Ch[(size_t)r0 * N + col]       = packh2(v00, v01);
                *(uint32_t*)&Ch[(size_t)(r0 + 8) * N + col] = packh2(v10, v11);
            } else {
                *(float2*)&Cf[(size_t)r0 * N + col]       = make_float2(v00, v01);
                *(float2*)&Cf[(size_t)(r0 + 8) * N + col] = make_float2(v10, v11);
            }
        }
    }
}

// ---------------------------------------------------------------------------
// Flash attention, fp16 tensor cores, causal.
// 128 threads (4 warps), 64-query tile; warp w owns rows w*16..w*16+15.
// K/V tiles fp16 in smem (cp.async, 2-stage double buffer), SW128-style
// swizzle; K via ldmatrix, V via ldmatrix.trans; P stays in registers.
// ---------------------------------------------------------------------------
#define FST 16384   // per-stage bytes: K 8KB + V 8KB

__global__ void __launch_bounds__(128) flash_f16()
{
    __shared__ __align__(128) char fsm[2 * FST];
    const uint32_t sb = (uint32_t)__cvta_generic_to_shared(fsm);

    const int tid  = threadIdx.x;
    const int lane = tid & 31;
    const int g    = lane >> 2;
    const int t    = lane & 3;
    const int w    = tid >> 5;
    const int qt   = blockIdx.x;
    const int bh   = blockIdx.y;
    const int b    = bh >> 4;
    const int h    = bh & 15;
    const int q0   = qt * 64;

    // Q fragments (Q already scaled by 0.125 in GEMM1 epilogue)
    uint32_t qa[4][4];
    {
        const __half* qlo = g_qkvh + ((size_t)(q0 + w * 16 + g) * Bb + b) * QKVF + h * Dh;
        const __half* qhi = qlo + (size_t)8 * Bb * QKVF;
        #pragma unroll
        for (int ks = 0; ks < 4; ks++) {
            qa[ks][0] = *(const uint32_t*)(qlo + ks * 16 + 2 * t);
            qa[ks][1] = *(const uint32_t*)(qhi + ks * 16 + 2 * t);
            qa[ks][2] = *(const uint32_t*)(qlo + ks * 16 + 8 + 2 * t);
            qa[ks][3] = *(const uint32_t*)(qhi + ks * 16 + 8 + 2 * t);
        }
    }

    auto load_kv = [&](int st, int kt) {
        const uint32_t base = sb + st * FST;
        const int k0 = kt * 64;
        #pragma unroll
        for (int i = 0; i < 8; i++) {
            int q = tid + i * 128;
            int off, s, c;
            uint32_t dstb;
            if (q < 512) { s = q >> 3; c = q & 7; off = Ee;     dstb = base; }
            else { int q2 = q - 512; s = q2 >> 3; c = q2 & 7; off = 2 * Ee; dstb = base + 8192; }
            const __half* src = g_qkvh + ((size_t)(k0 + s) * Bb + b) * QKVF + off + h * Dh + c * 8;
            uint32_t dst = dstb + s * 128 + ((c ^ (s & 7)) << 4);
            asm volatile("cp.async.cg.shared.global [%0], [%1], 16;" :: "r"(dst), "l"(src));
        }
        asm volatile("cp.async.commit_group;" ::: "memory");
    };

    load_kv(0, 0);

    float o[8][4];
    #pragma unroll
    for (int nt = 0; nt < 8; nt++)
        #pragma unroll
        for (int i = 0; i < 4; i++) o[nt][i] = 0.0f;
    float m0v = -1e30f, m1v = -1e30f, l0 = 0.0f, l1 = 0.0f;

    const int krl = ((lane >> 4) & 1) * 8 + (lane & 7);
    const int kck = (lane >> 3) & 1;
    const int vrl = ((lane >> 3) & 1) * 8 + (lane & 7);
    const int vck = lane >> 4;

    for (int kt = 0; kt <= qt; kt++) {
        asm volatile("cp.async.wait_group 0;" ::: "memory");
        __syncthreads();
        if (kt < qt) load_kv((kt + 1) & 1, kt + 1);

        const uint32_t Kb = sb + (kt & 1) * FST;
        const uint32_t Vb = Kb + 8192;

        // S = Q K^T
        float sv[8][4];
        #pragma unroll
        for (int nt = 0; nt < 8; nt++)
            #pragma unroll
            for (int i = 0; i < 4; i++) sv[nt][i] = 0.0f;

        #pragma unroll
        for (int ks = 0; ks < 4; ks++) {
            #pragma unroll
            for (int p = 0; p < 4; p++) {
                int n = p * 16 + krl;
                int ch = (2 * ks + kck) ^ (n & 7);
                uint32_t r0, r1, r2, r3;
                ldsm4(r0, r1, r2, r3, Kb + n * 128 + (ch << 4));
                mma16(sv[2 * p],     qa[ks][0], qa[ks][1], qa[ks][2], qa[ks][3], r0, r1);
                mma16(sv[2 * p + 1], qa[ks][0], qa[ks][1], qa[ks][2], qa[ks][3], r2, r3);
            }
        }

        // Causal mask (diagonal tile only)
        if (kt == qt) {
            const int r_lo = w * 16 + g, r_hi = r_lo + 8;
            #pragma unroll
            for (int nt = 0; nt < 8; nt++) {
                const int c0 = nt * 8 + 2 * t, c1 = c0 + 1;
                if (c0 > r_lo) sv[nt][0] = -1e30f;
                if (c1 > r_lo) sv[nt][1] = -1e30f;
                if (c0 > r_hi) sv[nt][2] = -1e30f;
                if (c1 > r_hi) sv[nt][3] = -1e30f;
            }
        }

        // Online softmax
        float mx0 = -1e30f, mx1 = -1e30f;
        #pragma unroll
        for (int nt = 0; nt < 8; nt++) {
            mx0 = fmaxf(mx0, fmaxf(sv[nt][0], sv[nt][1]));
            mx1 = fmaxf(mx1, fmaxf(sv[nt][2], sv[nt][3]));
        }
        mx0 = fmaxf(mx0, __shfl_xor_sync(0xffffffffu, mx0, 1));
        mx0 = fmaxf(mx0, __shfl_xor_sync(0xffffffffu, mx0, 2));
        mx1 = fmaxf(mx1, __shfl_xor_sync(0xffffffffu, mx1, 1));
        mx1 = fmaxf(mx1, __shfl_xor_sync(0xffffffffu, mx1, 2));

        const float mn0 = fmaxf(m0v, mx0), mn1 = fmaxf(m1v, mx1);
        const float al0 = __expf(m0v - mn0), al1 = __expf(m1v - mn1);
        m0v = mn0; m1v = mn1;

        float sum0 = 0.0f, sum1 = 0.0f;
        #pragma unroll
        for (int nt = 0; nt < 8; nt++) {
            sv[nt][0] = __expf(sv[nt][0] - mn0); sum0 += sv[nt][0];
            sv[nt][1] = __expf(sv[nt][1] - mn0); sum0 += sv[nt][1];
            sv[nt][2] = __expf(sv[nt][2] - mn1); sum1 += sv[nt][2];
            sv[nt][3] = __expf(sv[nt][3] - mn1); sum1 += sv[nt][3];
        }
        sum0 += __shfl_xor_sync(0xffffffffu, sum0, 1);
        sum0 += __shfl_xor_sync(0xffffffffu, sum0, 2);
        sum1 += __shfl_xor_sync(0xffffffffu, sum1, 1);
        sum1 += __shfl_xor_sync(0xffffffffu, sum1, 2);
        l0 = l0 * al0 + sum0;
        l1 = l1 * al1 + sum1;

        #pragma unroll
        for (int nt = 0; nt < 8; nt++) {
            o[nt][0] *= al0; o[nt][1] *= al0;
            o[nt][2] *= al1; o[nt][3] *= al1;
        }

        // O += P V  (P register-resident, packed to fp16)
        #pragma unroll
        for (int ks = 0; ks < 4; ks++) {
            const uint32_t p0 = packh2(sv[2 * ks][0],     sv[2 * ks][1]);
            const uint32_t p1 = packh2(sv[2 * ks][2],     sv[2 * ks][3]);
            const uint32_t p2 = packh2(sv[2 * ks + 1][0], sv[2 * ks + 1][1]);
            const uint32_t p3 = packh2(sv[2 * ks + 1][2], sv[2 * ks + 1][3]);
            #pragma unroll
            for (int p = 0; p < 4; p++) {
                int srow = ks * 16 + vrl;
                int ch = (2 * p + vck) ^ (srow & 7);
                uint32_t r0, r1, r2, r3;
                ldsm4t(r0, r1, r2, r3, Vb + srow * 128 + (ch << 4));
                mma16(o[2 * p],     p0, p1, p2, p3, r0, r1);
                mma16(o[2 * p + 1], p0, p1, p2, p3, r2, r3);
            }
        }
    }

    // Epilogue: normalize, write fp16 [T,B,E]
    const float inv0 = 1.0f / l0, inv1 = 1.0f / l1;
    __half* dlo = g_atth + ((size_t)(q0 + w * 16 + g) * Bb + b) * Ee + h * Dh;
    __half* dhi = dlo + (size_t)8 * Bb * Ee;
    #pragma unroll
    for (int nt = 0; nt < 8; nt++) {
        const int c = nt * 8 + 2 * t;
        *(uint32_t*)&dlo[c] = packh2(o[nt][0] * inv0, o[nt][1] * inv0);
        *(uint32_t*)&dhi[c] = packh2(o[nt][2] * inv1, o[nt][3] * inv1);
    }
}

// ---------------------------------------------------------------------------
// Launch
// ---------------------------------------------------------------------------
extern "C" void kernel_launch(void* const* d_in, const int* in_sizes, int n_in,
                              void* d_out, int out_size)
{
    const float* query = (const float*)d_in[0];
    const float* qkv_w = (const float*)d_in[1];
    const float* qkv_b = (const float*)d_in[2];
    const float* out_w = (const float*)d_in[3];
    const float* out_b = (const float*)d_in[4];
    float* out = (float*)d_out;

    void *p_xh = nullptr, *p_w1h = nullptr, *p_w2h = nullptr,
         *p_qkvh = nullptr, *p_atth = nullptr;
    cudaGetSymbolAddress(&p_xh,   g_xh);
    cudaGetSymbolAddress(&p_w1h,  g_w1h);
    cudaGetSymbolAddress(&p_w2h,  g_w2h);
    cudaGetSymbolAddress(&p_qkvh, g_qkvh);
    cudaGetSymbolAddress(&p_atth, g_atth);

    cudaFuncSetAttribute(gemm_f16, cudaFuncAttributeMaxDynamicSharedMemorySize, GSM);

    // 0) fp32 -> fp16 prepass
    cvt_f32_f16<<<(MROWS * Ee / 4 + 255) / 256, 256>>>((const float4*)query, (uint2*)p_xh,  MROWS * Ee / 4);
    cvt_f32_f16<<<(QKVF  * Ee / 4 + 255) / 256, 256>>>((const float4*)qkv_w, (uint2*)p_w1h, QKVF  * Ee / 4);
    cvt_f32_f16<<<(Ee    * Ee / 4 + 255) / 256, 256>>>((const float4*)out_w, (uint2*)p_w2h, Ee    * Ee / 4);

    // 1) QKV projection -> fp16, Q block scaled by 0.125
    gemm_f16<<<dim3(QKVF / BN, MROWS / BM), 256, GSM>>>(
        (const __half*)p_xh, (const __half*)p_w1h, qkv_b,
        (__half*)p_qkvh, nullptr, MROWS, QKVF, Ee, 1);

    // 2) Causal flash attention per (query-tile, b*H+h)
    flash_f16<<<dim3(Tt / 64, Bb * Hh), 128>>>();

    // 3) Output projection -> fp32 final output
    gemm_f16<<<dim3(Ee / BN, MROWS / BM), 256, GSM>>>(
        (const __half*)p_atth, (const __half*)p_w2h, out_b,
        nullptr, out, MROWS, Ee, Ee, 0);
}

// round 5
// speedup vs baseline: 6.6535x; 1.2009x over previous
#include <cuda_runtime.h>
#include <cuda_fp16.h>
#include <cstdint>

// Problem constants
#define Tt    1024
#define Bb    8
#define Ee    1024
#define Hh    16
#define Dh    64
#define QKVF  3072           // 3*E
#define MROWS 8192           // T*B

// Scratch (device globals — no runtime allocation allowed)
__device__ __half g_xh  [(size_t)MROWS * Ee];    // query, fp16
__device__ __half g_w1h [(size_t)QKVF * Ee];     // qkv_w, fp16
__device__ __half g_w2h [(size_t)Ee * Ee];       // out_w, fp16
__device__ __half g_qkvh[(size_t)MROWS * QKVF];  // qkv proj out (Q pre-scaled), fp16
__device__ __half g_atth[(size_t)MROWS * Ee];    // attention out, fp16

// ---------------------------------------------------------------------------
// Helpers
// ---------------------------------------------------------------------------
__device__ __forceinline__ uint32_t packh2(float lo, float hi) {
    __half2 h = __floats2half2_rn(lo, hi);
    return *reinterpret_cast<uint32_t*>(&h);
}

__device__ __forceinline__ void mma16(float* c,
                                      uint32_t a0, uint32_t a1, uint32_t a2, uint32_t a3,
                                      uint32_t b0, uint32_t b1) {
    asm volatile("mma.sync.aligned.m16n8k16.row.col.f32.f16.f16.f32 "
                 "{%0,%1,%2,%3}, {%4,%5,%6,%7}, {%8,%9}, {%0,%1,%2,%3};"
                 : "+f"(c[0]), "+f"(c[1]), "+f"(c[2]), "+f"(c[3])
                 : "r"(a0), "r"(a1), "r"(a2), "r"(a3), "r"(b0), "r"(b1));
}

__device__ __forceinline__ void ldsm4(uint32_t& r0, uint32_t& r1, uint32_t& r2, uint32_t& r3,
                                      uint32_t addr) {
    asm volatile("ldmatrix.sync.aligned.m8n8.x4.shared.b16 {%0,%1,%2,%3}, [%4];"
                 : "=r"(r0), "=r"(r1), "=r"(r2), "=r"(r3) : "r"(addr));
}

__device__ __forceinline__ void ldsm4t(uint32_t& r0, uint32_t& r1, uint32_t& r2, uint32_t& r3,
                                       uint32_t addr) {
    asm volatile("ldmatrix.sync.aligned.m8n8.x4.trans.shared.b16 {%0,%1,%2,%3}, [%4];"
                 : "=r"(r0), "=r"(r1), "=r"(r2), "=r"(r3) : "r"(addr));
}

// ---------------------------------------------------------------------------
// Prepass: fp32 -> fp16 (RN)
// ---------------------------------------------------------------------------
__global__ void cvt_f32_f16(const float4* __restrict__ in, uint2* __restrict__ out, int n4) {
    int i = blockIdx.x * blockDim.x + threadIdx.x;
    if (i < n4) {
        float4 v = in[i];
        uint2 o;
        o.x = packh2(v.x, v.y);
        o.y = packh2(v.z, v.w);
        out[i] = o;
    }
}

// ---------------------------------------------------------------------------
// fp16 tensor-core GEMM (NT): C[M,N] = A[M,K]*B[N,K]^T, epilogue (acc+bias)*scale
// CTA tile 128x128, 8 warps (2m x 4n), warp tile 64x32, BK=32 halfs.
// 4-stage cp.async pipeline, 16KB/stage = 64KB smem -> 2 CTAs/SM.
// Smem rows: 64B (4 x 16B chunks), chunk swizzle c ^ ((row>>1)&3).
// ---------------------------------------------------------------------------
#define BM  128
#define BN  128
#define BKH 32
#define NSG 4
#define ABY (BM * 64)          // 8192
#define BBY (BN * 64)          // 8192
#define STG (ABY + BBY)        // 16384
#define GSM (NSG * STG)        // 65536

__global__ void __launch_bounds__(256, 2) gemm_f16(
    const __half* __restrict__ Ah, const __half* __restrict__ Bh,
    const float* __restrict__ bias, __half* __restrict__ Ch, float* __restrict__ Cf,
    int M, int N, int K, int qscale)
{
    extern __shared__ char smem[];
    const uint32_t sb = (uint32_t)__cvta_generic_to_shared(smem);
    const int tid  = threadIdx.x;
    const int lane = tid & 31;
    const int warp = tid >> 5;
    const int wm = warp & 1;
    const int wn = warp >> 1;
    const int m0 = blockIdx.y * BM;
    const int n0 = blockIdx.x * BN;

    float acc[4][4][4];
    #pragma unroll
    for (int mt = 0; mt < 4; mt++)
        #pragma unroll
        for (int nt = 0; nt < 4; nt++)
            #pragma unroll
            for (int i = 0; i < 4; i++) acc[mt][nt][i] = 0.0f;

    auto load_stage = [&](int s, int c) {
        const uint32_t base = sb + s * STG;
        const int k0 = c * BKH;
        #pragma unroll
        for (int i = 0; i < 4; i++) {
            int q = tid + i * 256;
            uint32_t dst;
            const __half* src;
            if (q < 512) {                   // A: 128 rows x 4 chunks
                int r = q >> 2, ch = q & 3;
                src = Ah + (size_t)(m0 + r) * K + k0 + ch * 8;
                dst = base + r * 64 + ((ch ^ ((r >> 1) & 3)) << 4);
            } else {                         // B: 128 rows x 4 chunks
                int q2 = q - 512;
                int r = q2 >> 2, ch = q2 & 3;
                src = Bh + (size_t)(n0 + r) * K + k0 + ch * 8;
                dst = base + ABY + r * 64 + ((ch ^ ((r >> 1) & 3)) << 4);
            }
            asm volatile("cp.async.cg.shared.global [%0], [%1], 16;" :: "r"(dst), "l"(src));
        }
        asm volatile("cp.async.commit_group;" ::: "memory");
    };

    const int nk = K / BKH;
    load_stage(0, 0);
    load_stage(1, 1);
    load_stage(2, 2);

    const int a_rl = ((lane >> 3) & 1) * 8 + (lane & 7);
    const int a_ck = lane >> 4;
    const int b_rl = ((lane >> 4) & 1) * 8 + (lane & 7);
    const int b_ck = (lane >> 3) & 1;

    for (int c = 0; c < nk; c++) {
        const int s = c & (NSG - 1);
        if (c < nk - 1) asm volatile("cp.async.wait_group 2;" ::: "memory");
        else            asm volatile("cp.async.wait_group 0;" ::: "memory");
        __syncthreads();
        if (c + NSG - 1 < nk) load_stage((c + NSG - 1) & (NSG - 1), c + NSG - 1);

        const uint32_t abase = sb + s * STG;
        const uint32_t bbase = abase + ABY;
        #pragma unroll
        for (int ks = 0; ks < 2; ks++) {
            uint32_t af[4][4], bf[4][2];
            #pragma unroll
            for (int mt = 0; mt < 4; mt++) {
                int ar = wm * 64 + mt * 16 + a_rl;
                int ch = (2 * ks + a_ck) ^ ((ar >> 1) & 3);
                ldsm4(af[mt][0], af[mt][1], af[mt][2], af[mt][3],
                      abase + ar * 64 + (ch << 4));
            }
            #pragma unroll
            for (int p = 0; p < 2; p++) {
                int br = wn * 32 + p * 16 + b_rl;
                int ch = (2 * ks + b_ck) ^ ((br >> 1) & 3);
                uint32_t r0, r1, r2, r3;
                ldsm4(r0, r1, r2, r3, bbase + br * 64 + (ch << 4));
                bf[2 * p][0] = r0;     bf[2 * p][1] = r1;
                bf[2 * p + 1][0] = r2; bf[2 * p + 1][1] = r3;
            }
            #pragma unroll
            for (int mt = 0; mt < 4; mt++)
                #pragma unroll
                for (int nt = 0; nt < 4; nt++)
                    mma16(acc[mt][nt], af[mt][0], af[mt][1], af[mt][2], af[mt][3],
                          bf[nt][0], bf[nt][1]);
        }
    }

    // Epilogue
    const float scale = (qscale && n0 < Ee) ? 0.125f : 1.0f;
    const int g = lane >> 2, t = lane & 3;
    #pragma unroll
    for (int mt = 0; mt < 4; mt++) {
        const int r0 = m0 + wm * 64 + mt * 16 + g;
        #pragma unroll
        for (int nt = 0; nt < 4; nt++) {
            const int col = n0 + wn * 32 + nt * 8 + 2 * t;
            const float b0 = bias[col], b1 = bias[col + 1];
            float v00 = (acc[mt][nt][0] + b0) * scale;
            float v01 = (acc[mt][nt][1] + b1) * scale;
            float v10 = (acc[mt][nt][2] + b0) * scale;
            float v11 = (acc[mt][nt][3] + b1) * scale;
            if (Ch) {
                *(uint32_t*)&Ch[(size_t)r0 * N + col]       = packh2(v00, v01);
                *(uint32_t*)&Ch[(size_t)(r0 + 8) * N + col] = packh2(v10, v11);
            } else {
                *(float2*)&Cf[(size_t)r0 * N + col]       = make_float2(v00, v01);
                *(float2*)&Cf[(size_t)(r0 + 8) * N + col] = make_float2(v10, v11);
            }
        }
    }
}

// ---------------------------------------------------------------------------
// Flash attention, fp16 tensor cores, causal (unchanged from R4).
// ---------------------------------------------------------------------------
#define FST 16384   // per-stage bytes: K 8KB + V 8KB

__global__ void __launch_bounds__(128) flash_f16()
{
    __shared__ __align__(128) char fsm[2 * FST];
    const uint32_t sb = (uint32_t)__cvta_generic_to_shared(fsm);

    const int tid  = threadIdx.x;
    const int lane = tid & 31;
    const int g    = lane >> 2;
    const int t    = lane & 3;
    const int w    = tid >> 5;
    const int qt   = blockIdx.x;
    const int bh   = blockIdx.y;
    const int b    = bh >> 4;
    const int h    = bh & 15;
    const int q0   = qt * 64;

    // Q fragments (Q already scaled by 0.125 in GEMM1 epilogue)
    uint32_t qa[4][4];
    {
        const __half* qlo = g_qkvh + ((size_t)(q0 + w * 16 + g) * Bb + b) * QKVF + h * Dh;
        const __half* qhi = qlo + (size_t)8 * Bb * QKVF;
        #pragma unroll
        for (int ks = 0; ks < 4; ks++) {
            qa[ks][0] = *(const uint32_t*)(qlo + ks * 16 + 2 * t);
            qa[ks][1] = *(const uint32_t*)(qhi + ks * 16 + 2 * t);
            qa[ks][2] = *(const uint32_t*)(qlo + ks * 16 + 8 + 2 * t);
            qa[ks][3] = *(const uint32_t*)(qhi + ks * 16 + 8 + 2 * t);
        }
    }

    auto load_kv = [&](int st, int kt) {
        const uint32_t base = sb + st * FST;
        const int k0 = kt * 64;
        #pragma unroll
        for (int i = 0; i < 8; i++) {
            int q = tid + i * 128;
            int off, s, c;
            uint32_t dstb;
            if (q < 512) { s = q >> 3; c = q & 7; off = Ee;     dstb = base; }
            else { int q2 = q - 512; s = q2 >> 3; c = q2 & 7; off = 2 * Ee; dstb = base + 8192; }
            const __half* src = g_qkvh + ((size_t)(k0 + s) * Bb + b) * QKVF + off + h * Dh + c * 8;
            uint32_t dst = dstb + s * 128 + ((c ^ (s & 7)) << 4);
            asm volatile("cp.async.cg.shared.global [%0], [%1], 16;" :: "r"(dst), "l"(src));
        }
        asm volatile("cp.async.commit_group;" ::: "memory");
    };

    load_kv(0, 0);

    float o[8][4];
    #pragma unroll
    for (int nt = 0; nt < 8; nt++)
        #pragma unroll
        for (int i = 0; i < 4; i++) o[nt][i] = 0.0f;
    float m0v = -1e30f, m1v = -1e30f, l0 = 0.0f, l1 = 0.0f;

    const int krl = ((lane >> 4) & 1) * 8 + (lane & 7);
    const int kck = (lane >> 3) & 1;
    const int vrl = ((lane >> 3) & 1) * 8 + (lane & 7);
    const int vck = lane >> 4;

    for (int kt = 0; kt <= qt; kt++) {
        asm volatile("cp.async.wait_group 0;" ::: "memory");
        __syncthreads();
        if (kt < qt) load_kv((kt + 1) & 1, kt + 1);

        const uint32_t Kb = sb + (kt & 1) * FST;
        const uint32_t Vb = Kb + 8192;

        // S = Q K^T
        float sv[8][4];
        #pragma unroll
        for (int nt = 0; nt < 8; nt++)
            #pragma unroll
            for (int i = 0; i < 4; i++) sv[nt][i] = 0.0f;

        #pragma unroll
        for (int ks = 0; ks < 4; ks++) {
            #pragma unroll
            for (int p = 0; p < 4; p++) {
                int n = p * 16 + krl;
                int ch = (2 * ks + kck) ^ (n & 7);
                uint32_t r0, r1, r2, r3;
                ldsm4(r0, r1, r2, r3, Kb + n * 128 + (ch << 4));
                mma16(sv[2 * p],     qa[ks][0], qa[ks][1], qa[ks][2], qa[ks][3], r0, r1);
                mma16(sv[2 * p + 1], qa[ks][0], qa[ks][1], qa[ks][2], qa[ks][3], r2, r3);
            }
        }

        // Causal mask (diagonal tile only)
        if (kt == qt) {
            const int r_lo = w * 16 + g, r_hi = r_lo + 8;
            #pragma unroll
            for (int nt = 0; nt < 8; nt++) {
                const int c0 = nt * 8 + 2 * t, c1 = c0 + 1;
                if (c0 > r_lo) sv[nt][0] = -1e30f;
                if (c1 > r_lo) sv[nt][1] = -1e30f;
                if (c0 > r_hi) sv[nt][2] = -1e30f;
                if (c1 > r_hi) sv[nt][3] = -1e30f;
            }
        }

        // Online softmax
        float mx0 = -1e30f, mx1 = -1e30f;
        #pragma unroll
        for (int nt = 0; nt < 8; nt++) {
            mx0 = fmaxf(mx0, fmaxf(sv[nt][0], sv[nt][1]));
            mx1 = fmaxf(mx1, fmaxf(sv[nt][2], sv[nt][3]));
        }
        mx0 = fmaxf(mx0, __shfl_xor_sync(0xffffffffu, mx0, 1));
        mx0 = fmaxf(mx0, __shfl_xor_sync(0xffffffffu, mx0, 2));
        mx1 = fmaxf(mx1, __shfl_xor_sync(0xffffffffu, mx1, 1));
        mx1 = fmaxf(mx1, __shfl_xor_sync(0xffffffffu, mx1, 2));

        const float mn0 = fmaxf(m0v, mx0), mn1 = fmaxf(m1v, mx1);
        const float al0 = __expf(m0v - mn0), al1 = __expf(m1v - mn1);
        m0v = mn0; m1v = mn1;

        float sum0 = 0.0f, sum1 = 0.0f;
        #pragma unroll
        for (int nt = 0; nt < 8; nt++) {
            sv[nt][0] = __expf(sv[nt][0] - mn0); sum0 += sv[nt][0];
            sv[nt][1] = __expf(sv[nt][1] - mn0); sum0 += sv[nt][1];
            sv[nt][2] = __expf(sv[nt][2] - mn1); sum1 += sv[nt][2];
            sv[nt][3] = __expf(sv[nt][3] - mn1); sum1 += sv[nt][3];
        }
        sum0 += __shfl_xor_sync(0xffffffffu, sum0, 1);
        sum0 += __shfl_xor_sync(0xffffffffu, sum0, 2);
        sum1 += __shfl_xor_sync(0xffffffffu, sum1, 1);
        sum1 += __shfl_xor_sync(0xffffffffu, sum1, 2);
        l0 = l0 * al0 + sum0;
        l1 = l1 * al1 + sum1;

        #pragma unroll
        for (int nt = 0; nt < 8; nt++) {
            o[nt][0] *= al0; o[nt][1] *= al0;
            o[nt][2] *= al1; o[nt][3] *= al1;
        }

        // O += P V  (P register-resident, packed to fp16)
        #pragma unroll
        for (int ks = 0; ks < 4; ks++) {
            const uint32_t p0 = packh2(sv[2 * ks][0],     sv[2 * ks][1]);
            const uint32_t p1 = packh2(sv[2 * ks][2],     sv[2 * ks][3]);
            const uint32_t p2 = packh2(sv[2 * ks + 1][0], sv[2 * ks + 1][1]);
            const uint32_t p3 = packh2(sv[2 * ks + 1][2], sv[2 * ks + 1][3]);
            #pragma unroll
            for (int p = 0; p < 4; p++) {
                int srow = ks * 16 + vrl;
                int ch = (2 * p + vck) ^ (srow & 7);
                uint32_t r0, r1, r2, r3;
                ldsm4t(r0, r1, r2, r3, Vb + srow * 128 + (ch << 4));
                mma16(o[2 * p],     p0, p1, p2, p3, r0, r1);
                mma16(o[2 * p + 1], p0, p1, p2, p3, r2, r3);
            }
        }
    }

    // Epilogue: normalize, write fp16 [T,B,E]
    const float inv0 = 1.0f / l0, inv1 = 1.0f / l1;
    __half* dlo = g_atth + ((size_t)(q0 + w * 16 + g) * Bb + b) * Ee + h * Dh;
    __half* dhi = dlo + (size_t)8 * Bb * Ee;
    #pragma unroll
    for (int nt = 0; nt < 8; nt++) {
        const int c = nt * 8 + 2 * t;
        *(uint32_t*)&dlo[c] = packh2(o[nt][0] * inv0, o[nt][1] * inv0);
        *(uint32_t*)&dhi[c] = packh2(o[nt][2] * inv1, o[nt][3] * inv1);
    }
}

// ---------------------------------------------------------------------------
// Launch
// ---------------------------------------------------------------------------
extern "C" void kernel_launch(void* const* d_in, const int* in_sizes, int n_in,
                              void* d_out, int out_size)
{
    const float* query = (const float*)d_in[0];
    const float* qkv_w = (const float*)d_in[1];
    const float* qkv_b = (const float*)d_in[2];
    const float* out_w = (const float*)d_in[3];
    const float* out_b = (const float*)d_in[4];
    float* out = (float*)d_out;

    void *p_xh = nullptr, *p_w1h = nullptr, *p_w2h = nullptr,
         *p_qkvh = nullptr, *p_atth = nullptr;
    cudaGetSymbolAddress(&p_xh,   g_xh);
    cudaGetSymbolAddress(&p_w1h,  g_w1h);
    cudaGetSymbolAddress(&p_w2h,  g_w2h);
    cudaGetSymbolAddress(&p_qkvh, g_qkvh);
    cudaGetSymbolAddress(&p_atth, g_atth);

    cudaFuncSetAttribute(gemm_f16, cudaFuncAttributeMaxDynamicSharedMemorySize, GSM);

    // 0) fp32 -> fp16 prepass
    cvt_f32_f16<<<(MROWS * Ee / 4 + 255) / 256, 256>>>((const float4*)query, (uint2*)p_xh,  MROWS * Ee / 4);
    cvt_f32_f16<<<(QKVF  * Ee / 4 + 255) / 256, 256>>>((const float4*)qkv_w, (uint2*)p_w1h, QKVF  * Ee / 4);
    cvt_f32_f16<<<(Ee    * Ee / 4 + 255) / 256, 256>>>((const float4*)out_w, (uint2*)p_w2h, Ee    * Ee / 4);

    // 1) QKV projection -> fp16, Q block scaled by 0.125
    gemm_f16<<<dim3(QKVF / BN, MROWS / BM), 256, GSM>>>(
        (const __half*)p_xh, (const __half*)p_w1h, qkv_b,
        (__half*)p_qkvh, nullptr, MROWS, QKVF, Ee, 1);

    // 2) Causal flash attention per (query-tile, b*H+h)
    flash_f16<<<dim3(Tt / 64, Bb * Hh), 128>>>();

    // 3) Output projection -> fp32 final output
    gemm_f16<<<dim3(Ee / BN, MROWS / BM), 256, GSM>>>(
        (const __half*)p_atth, (const __half*)p_w2h, out_b,
        nullptr, out, MROWS, Ee, Ee, 0);
}

// round 7
// speedup vs baseline: 7.1618x; 1.0764x over previous
#include <cuda_runtime.h>
#include <cuda_fp16.h>
#include <cstdint>

// Problem constants
#define Tt    1024
#define Bb    8
#define Ee    1024
#define Hh    16
#define Dh    64
#define QKVF  3072           // 3*E
#define MROWS 8192           // T*B

// Scratch (device globals — no runtime allocation allowed)
__device__ __half g_xh  [(size_t)MROWS * Ee];    // query, fp16
__device__ __half g_w1h [(size_t)QKVF * Ee];     // qkv_w, fp16
__device__ __half g_w2h [(size_t)Ee * Ee];       // out_w, fp16
__device__ __half g_qkvh[(size_t)MROWS * QKVF];  // qkv proj out (Q pre-scaled), fp16
__device__ __half g_atth[(size_t)MROWS * Ee];    // attention out, fp16

// ---------------------------------------------------------------------------
// Helpers
// ---------------------------------------------------------------------------
__device__ __forceinline__ uint32_t packh2(float lo, float hi) {
    __half2 h = __floats2half2_rn(lo, hi);
    return *reinterpret_cast<uint32_t*>(&h);
}

__device__ __forceinline__ void mma16(float* c,
                                      uint32_t a0, uint32_t a1, uint32_t a2, uint32_t a3,
                                      uint32_t b0, uint32_t b1) {
    asm volatile("mma.sync.aligned.m16n8k16.row.col.f32.f16.f16.f32 "
                 "{%0,%1,%2,%3}, {%4,%5,%6,%7}, {%8,%9}, {%0,%1,%2,%3};"
                 : "+f"(c[0]), "+f"(c[1]), "+f"(c[2]), "+f"(c[3])
                 : "r"(a0), "r"(a1), "r"(a2), "r"(a3), "r"(b0), "r"(b1));
}

__device__ __forceinline__ void ldsm4(uint32_t& r0, uint32_t& r1, uint32_t& r2, uint32_t& r3,
                                      uint32_t addr) {
    asm volatile("ldmatrix.sync.aligned.m8n8.x4.shared.b16 {%0,%1,%2,%3}, [%4];"
                 : "=r"(r0), "=r"(r1), "=r"(r2), "=r"(r3) : "r"(addr));
}

__device__ __forceinline__ void ldsm4t(uint32_t& r0, uint32_t& r1, uint32_t& r2, uint32_t& r3,
                                       uint32_t addr) {
    asm volatile("ldmatrix.sync.aligned.m8n8.x4.trans.shared.b16 {%0,%1,%2,%3}, [%4];"
                 : "=r"(r0), "=r"(r1), "=r"(r2), "=r"(r3) : "r"(addr));
}

// ---------------------------------------------------------------------------
// Prepass: fp32 -> fp16 (RN)
// ---------------------------------------------------------------------------
__global__ void cvt_f32_f16(const float4* __restrict__ in, uint2* __restrict__ out, int n4) {
    int i = blockIdx.x * blockDim.x + threadIdx.x;
    if (i < n4) {
        float4 v = in[i];
        uint2 o;
        o.x = packh2(v.x, v.y);
        o.y = packh2(v.z, v.w);
        out[i] = o;
    }
}

// ---------------------------------------------------------------------------
// fp16 tensor-core GEMM (NT): C[M,N] = A[M,K]*B[N,K]^T, epilogue (acc+bias)*scale
// CTA tile 128x128, 4 warps (2m x 2n), warp tile 64x64, BK=32 halfs.
// 4-stage cp.async pipeline, 16KB/stage = 64KB smem -> 2 CTAs/SM.
// Smem rows: 64B (4 x 16B chunks), chunk swizzle c ^ ((row>>1)&3).
// Fragment smem offsets hoisted out of the k-loop.
// ---------------------------------------------------------------------------
#define BM  128
#define BN  128
#define BKH 32
#define NSG 4
#define ABY (BM * 64)          // 8192
#define BBY (BN * 64)          // 8192
#define STG (ABY + BBY)        // 16384
#define GSM (NSG * STG)        // 65536

__global__ void __launch_bounds__(128, 2) gemm_f16(
    const __half* __restrict__ Ah, const __half* __restrict__ Bh,
    const float* __restrict__ bias, __half* __restrict__ Ch, float* __restrict__ Cf,
    int M, int N, int K, int qscale)
{
    extern __shared__ char smem[];
    const uint32_t sb = (uint32_t)__cvta_generic_to_shared(smem);
    const int tid  = threadIdx.x;
    const int lane = tid & 31;
    const int warp = tid >> 5;
    const int wm = warp & 1;
    const int wn = warp >> 1;
    const int m0 = blockIdx.y * BM;
    const int n0 = blockIdx.x * BN;

    float acc[4][8][4];
    #pragma unroll
    for (int mt = 0; mt < 4; mt++)
        #pragma unroll
        for (int nt = 0; nt < 8; nt++)
            #pragma unroll
            for (int i = 0; i < 4; i++) acc[mt][nt][i] = 0.0f;

    auto load_stage = [&](int s, int c) {
        const uint32_t base = sb + s * STG;
        const int k0 = c * BKH;
        #pragma unroll
        for (int i = 0; i < 8; i++) {
            int q = tid + i * 128;
            uint32_t dst;
            const __half* src;
            if (q < 512) {                   // A: 128 rows x 4 chunks
                int r = q >> 2, ch = q & 3;
                src = Ah + (size_t)(m0 + r) * K + k0 + ch * 8;
                dst = base + r * 64 + ((ch ^ ((r >> 1) & 3)) << 4);
            } else {                         // B: 128 rows x 4 chunks
                int q2 = q - 512;
                int r = q2 >> 2, ch = q2 & 3;
                src = Bh + (size_t)(n0 + r) * K + k0 + ch * 8;
                dst = base + ABY + r * 64 + ((ch ^ ((r >> 1) & 3)) << 4);
            }
            asm volatile("cp.async.cg.shared.global [%0], [%1], 16;" :: "r"(dst), "l"(src));
        }
        asm volatile("cp.async.commit_group;" ::: "memory");
    };

    const int nk = K / BKH;
    load_stage(0, 0);
    load_stage(1, 1);
    load_stage(2, 2);

    const int a_rl = ((lane >> 3) & 1) * 8 + (lane & 7);
    const int a_ck = lane >> 4;
    const int b_rl = ((lane >> 4) & 1) * 8 + (lane & 7);
    const int b_ck = (lane >> 3) & 1;

    // Hoisted fragment byte offsets within a stage (per ks-half, per tile)
    uint32_t aoff[2][4], boff[2][4];
    #pragma unroll
    for (int ks = 0; ks < 2; ks++) {
        #pragma unroll
        for (int mt = 0; mt < 4; mt++) {
            int ar = wm * 64 + mt * 16 + a_rl;
            int ch = (2 * ks + a_ck) ^ ((ar >> 1) & 3);
            aoff[ks][mt] = ar * 64 + (ch << 4);
        }
        #pragma unroll
        for (int p = 0; p < 4; p++) {
            int br = wn * 64 + p * 16 + b_rl;
            int ch = (2 * ks + b_ck) ^ ((br >> 1) & 3);
            boff[ks][p] = ABY + br * 64 + (ch << 4);
        }
    }

    for (int c = 0; c < nk; c++) {
        const int s = c & (NSG - 1);
        if (c < nk - 1) asm volatile("cp.async.wait_group 2;" ::: "memory");
        else            asm volatile("cp.async.wait_group 0;" ::: "memory");
        __syncthreads();
        if (c + NSG - 1 < nk) load_stage((c + NSG - 1) & (NSG - 1), c + NSG - 1);

        const uint32_t base = sb + s * STG;
        #pragma unroll
        for (int ks = 0; ks < 2; ks++) {
            uint32_t af[4][4], bf[8][2];
            #pragma unroll
            for (int mt = 0; mt < 4; mt++)
                ldsm4(af[mt][0], af[mt][1], af[mt][2], af[mt][3], base + aoff[ks][mt]);
            #pragma unroll
            for (int p = 0; p < 4; p++) {
                uint32_t r0, r1, r2, r3;
                ldsm4(r0, r1, r2, r3, base + boff[ks][p]);
                bf[2 * p][0] = r0;     bf[2 * p][1] = r1;
                bf[2 * p + 1][0] = r2; bf[2 * p + 1][1] = r3;
            }
            #pragma unroll
            for (int mt = 0; mt < 4; mt++)
                #pragma unroll
                for (int nt = 0; nt < 8; nt++)
                    mma16(acc[mt][nt], af[mt][0], af[mt][1], af[mt][2], af[mt][3],
                          bf[nt][0], bf[nt][1]);
        }
    }

    // Epilogue
    const float scale = (qscale && n0 < Ee) ? 0.125f : 1.0f;
    const int g = lane >> 2, t = lane & 3;
    #pragma unroll
    for (int mt = 0; mt < 4; mt++) {
        const int r0 = m0 + wm * 64 + mt * 16 + g;
        #pragma unroll
        for (int nt = 0; nt < 8; nt++) {
            const int col = n0 + wn * 64 + nt * 8 + 2 * t;
            const float b0 = bias[col], b1 = bias[col + 1];
            float v00 = (acc[mt][nt][0] + b0) * scale;
            float v01 = (acc[mt][nt][1] + b1) * scale;
            float v10 = (acc[mt][nt][2] + b0) * scale;
            float v11 = (acc[mt][nt][3] + b1) * scale;
            if (Ch) {
                *(uint32_t*)&Ch[(size_t)r0 * N + col]       = packh2(v00, v01);
                *(uint32_t*)&Ch[(size_t)(r0 + 8) * N + col] = packh2(v10, v11);
            } else {
                *(float2*)&Cf[(size_t)r0 * N + col]       = make_float2(v00, v01);
                *(float2*)&Cf[(size_t)(r0 + 8) * N + col] = make_float2(v10, v11);
            }
        }
    }
}

// ---------------------------------------------------------------------------
// Flash attention, fp16 tensor cores, causal (unchanged from R5).
// ---------------------------------------------------------------------------
#define FST 16384   // per-stage bytes: K 8KB + V 8KB

__global__ void __launch_bounds__(128) flash_f16()
{
    __shared__ __align__(128) char fsm[2 * FST];
    const uint32_t sb = (uint32_t)__cvta_generic_to_shared(fsm);

    const int tid  = threadIdx.x;
    const int lane = tid & 31;
    const int g    = lane >> 2;
    const int t    = lane & 3;
    const int w    = tid >> 5;
    const int qt   = blockIdx.x;
    const int bh   = blockIdx.y;
    const int b    = bh >> 4;
    const int h    = bh & 15;
    const int q0   = qt * 64;

    // Q fragments (Q already scaled by 0.125 in GEMM1 epilogue)
    uint32_t qa[4][4];
    {
        const __half* qlo = g_qkvh + ((size_t)(q0 + w * 16 + g) * Bb + b) * QKVF + h * Dh;
        const __half* qhi = qlo + (size_t)8 * Bb * QKVF;
        #pragma unroll
        for (int ks = 0; ks < 4; ks++) {
            qa[ks][0] = *(const uint32_t*)(qlo + ks * 16 + 2 * t);
            qa[ks][1] = *(const uint32_t*)(qhi + ks * 16 + 2 * t);
            qa[ks][2] = *(const uint32_t*)(qlo + ks * 16 + 8 + 2 * t);
            qa[ks][3] = *(const uint32_t*)(qhi + ks * 16 + 8 + 2 * t);
        }
    }

    auto load_kv = [&](int st, int kt) {
        const uint32_t base = sb + st * FST;
        const int k0 = kt * 64;
        #pragma unroll
        for (int i = 0; i < 8; i++) {
            int q = tid + i * 128;
            int off, s, c;
            uint32_t dstb;
            if (q < 512) { s = q >> 3; c = q & 7; off = Ee;     dstb = base; }
            else { int q2 = q - 512; s = q2 >> 3; c = q2 & 7; off = 2 * Ee; dstb = base + 8192; }
            const __half* src = g_qkvh + ((size_t)(k0 + s) * Bb + b) * QKVF + off + h * Dh + c * 8;
            uint32_t dst = dstb + s * 128 + ((c ^ (s & 7)) << 4);
            asm volatile("cp.async.cg.shared.global [%0], [%1], 16;" :: "r"(dst), "l"(src));
        }
        asm volatile("cp.async.commit_group;" ::: "memory");
    };

    load_kv(0, 0);

    float o[8][4];
    #pragma unroll
    for (int nt = 0; nt < 8; nt++)
        #pragma unroll
        for (int i = 0; i < 4; i++) o[nt][i] = 0.0f;
    float m0v = -1e30f, m1v = -1e30f, l0 = 0.0f, l1 = 0.0f;

    const int krl = ((lane >> 4) & 1) * 8 + (lane & 7);
    const int kck = (lane >> 3) & 1;
    const int vrl = ((lane >> 3) & 1) * 8 + (lane & 7);
    const int vck = lane >> 4;

    for (int kt = 0; kt <= qt; kt++) {
        asm volatile("cp.async.wait_group 0;" ::: "memory");
        __syncthreads();
        if (kt < qt) load_kv((kt + 1) & 1, kt + 1);

        const uint32_t Kb = sb + (kt & 1) * FST;
        const uint32_t Vb = Kb + 8192;

        // S = Q K^T
        float sv[8][4];
        #pragma unroll
        for (int nt = 0; nt < 8; nt++)
            #pragma unroll
            for (int i = 0; i < 4; i++) sv[nt][i] = 0.0f;

        #pragma unroll
        for (int ks = 0; ks < 4; ks++) {
            #pragma unroll
            for (int p = 0; p < 4; p++) {
                int n = p * 16 + krl;
                int ch = (2 * ks + kck) ^ (n & 7);
                uint32_t r0, r1, r2, r3;
                ldsm4(r0, r1, r2, r3, Kb + n * 128 + (ch << 4));
                mma16(sv[2 * p],     qa[ks][0], qa[ks][1], qa[ks][2], qa[ks][3], r0, r1);
                mma16(sv[2 * p + 1], qa[ks][0], qa[ks][1], qa[ks][2], qa[ks][3], r2, r3);
            }
        }

        // Causal mask (diagonal tile only)
        if (kt == qt) {
            const int r_lo = w * 16 + g, r_hi = r_lo + 8;
            #pragma unroll
            for (int nt = 0; nt < 8; nt++) {
                const int c0 = nt * 8 + 2 * t, c1 = c0 + 1;
                if (c0 > r_lo) sv[nt][0] = -1e30f;
                if (c1 > r_lo) sv[nt][1] = -1e30f;
                if (c0 > r_hi) sv[nt][2] = -1e30f;
                if (c1 > r_hi) sv[nt][3] = -1e30f;
            }
        }

        // Online softmax
        float mx0 = -1e30f, mx1 = -1e30f;
        #pragma unroll
        for (int nt = 0; nt < 8; nt++) {
            mx0 = fmaxf(mx0, fmaxf(sv[nt][0], sv[nt][1]));
            mx1 = fmaxf(mx1, fmaxf(sv[nt][2], sv[nt][3]));
        }
        mx0 = fmaxf(mx0, __shfl_xor_sync(0xffffffffu, mx0, 1));
        mx0 = fmaxf(mx0, __shfl_xor_sync(0xffffffffu, mx0, 2));
        mx1 = fmaxf(mx1, __shfl_xor_sync(0xffffffffu, mx1, 1));
        mx1 = fmaxf(mx1, __shfl_xor_sync(0xffffffffu, mx1, 2));

        const float mn0 = fmaxf(m0v, mx0), mn1 = fmaxf(m1v, mx1);
        const float al0 = __expf(m0v - mn0), al1 = __expf(m1v - mn1);
        m0v = mn0; m1v = mn1;

        float sum0 = 0.0f, sum1 = 0.0f;
        #pragma unroll
        for (int nt = 0; nt < 8; nt++) {
            sv[nt][0] = __expf(sv[nt][0] - mn0); sum0 += sv[nt][0];
            sv[nt][1] = __expf(sv[nt][1] - mn0); sum0 += sv[nt][1];
            sv[nt][2] = __expf(sv[nt][2] - mn1); sum1 += sv[nt][2];
            sv[nt][3] = __expf(sv[nt][3] - mn1); sum1 += sv[nt][3];
        }
        sum0 += __shfl_xor_sync(0xffffffffu, sum0, 1);
        sum0 += __shfl_xor_sync(0xffffffffu, sum0, 2);
        sum1 += __shfl_xor_sync(0xffffffffu, sum1, 1);
        sum1 += __shfl_xor_sync(0xffffffffu, sum1, 2);
        l0 = l0 * al0 + sum0;
        l1 = l1 * al1 + sum1;

        #pragma unroll
        for (int nt = 0; nt < 8; nt++) {
            o[nt][0] *= al0; o[nt][1] *= al0;
            o[nt][2] *= al1; o[nt][3] *= al1;
        }

        // O += P V  (P register-resident, packed to fp16)
        #pragma unroll
        for (int ks = 0; ks < 4; ks++) {
            const uint32_t p0 = packh2(sv[2 * ks][0],     sv[2 * ks][1]);
            const uint32_t p1 = packh2(sv[2 * ks][2],     sv[2 * ks][3]);
            const uint32_t p2 = packh2(sv[2 * ks + 1][0], sv[2 * ks + 1][1]);
            const uint32_t p3 = packh2(sv[2 * ks + 1][2], sv[2 * ks + 1][3]);
            #pragma unroll
            for (int p = 0; p < 4; p++) {
                int srow = ks * 16 + vrl;
                int ch = (2 * p + vck) ^ (srow & 7);
                uint32_t r0, r1, r2, r3;
                ldsm4t(r0, r1, r2, r3, Vb + srow * 128 + (ch << 4));
                mma16(o[2 * p],     p0, p1, p2, p3, r0, r1);
                mma16(o[2 * p + 1], p0, p1, p2, p3, r2, r3);
            }
        }
    }

    // Epilogue: normalize, write fp16 [T,B,E]
    const float inv0 = 1.0f / l0, inv1 = 1.0f / l1;
    __half* dlo = g_atth + ((size_t)(q0 + w * 16 + g) * Bb + b) * Ee + h * Dh;
    __half* dhi = dlo + (size_t)8 * Bb * Ee;
    #pragma unroll
    for (int nt = 0; nt < 8; nt++) {
        const int c = nt * 8 + 2 * t;
        *(uint32_t*)&dlo[c] = packh2(o[nt][0] * inv0, o[nt][1] * inv0);
        *(uint32_t*)&dhi[c] = packh2(o[nt][2] * inv1, o[nt][3] * inv1);
    }
}

// ---------------------------------------------------------------------------
// Launch
// ---------------------------------------------------------------------------
extern "C" void kernel_launch(void* const* d_in, const int* in_sizes, int n_in,
                              void* d_out, int out_size)
{
    const float* query = (const float*)d_in[0];
    const float* qkv_w = (const float*)d_in[1];
    const float* qkv_b = (const float*)d_in[2];
    const float* out_w = (const float*)d_in[3];
    const float* out_b = (const float*)d_in[4];
    float* out = (float*)d_out;

    void *p_xh = nullptr, *p_w1h = nullptr, *p_w2h = nullptr,
         *p_qkvh = nullptr, *p_atth = nullptr;
    cudaGetSymbolAddress(&p_xh,   g_xh);
    cudaGetSymbolAddress(&p_w1h,  g_w1h);
    cudaGetSymbolAddress(&p_w2h,  g_w2h);
    cudaGetSymbolAddress(&p_qkvh, g_qkvh);
    cudaGetSymbolAddress(&p_atth, g_atth);

    cudaFuncSetAttribute(gemm_f16, cudaFuncAttributeMaxDynamicSharedMemorySize, GSM);

    // 0) fp32 -> fp16 prepass
    cvt_f32_f16<<<(MROWS * Ee / 4 + 255) / 256, 256>>>((const float4*)query, (uint2*)p_xh,  MROWS * Ee / 4);
    cvt_f32_f16<<<(QKVF  * Ee / 4 + 255) / 256, 256>>>((const float4*)qkv_w, (uint2*)p_w1h, QKVF  * Ee / 4);
    cvt_f32_f16<<<(Ee    * Ee / 4 + 255) / 256, 256>>>((const float4*)out_w, (uint2*)p_w2h, Ee    * Ee / 4);

    // 1) QKV projection -> fp16, Q block scaled by 0.125
    gemm_f16<<<dim3(QKVF / BN, MROWS / BM), 128, GSM>>>(
        (const __half*)p_xh, (const __half*)p_w1h, qkv_b,
        (__half*)p_qkvh, nullptr, MROWS, QKVF, Ee, 1);

    // 2) Causal flash attention per (query-tile, b*H+h)
    flash_f16<<<dim3(Tt / 64, Bb * Hh), 128>>>();

    // 3) Output projection -> fp32 final output
    gemm_f16<<<dim3(Ee / BN, MROWS / BM), 128, GSM>>>(
        (const __half*)p_atth, (const __half*)p_w2h, out_b,
        nullptr, out, MROWS, Ee, Ee, 0);
}